// round 12
// baseline (speedup 1.0000x reference)
#include <cuda_runtime.h>
#include <cuda_bf16.h>
#include <cstdint>

// u_quant_weight_linear: out[o,i] = clip(rint(w[o,i]/s), -qmax, qmax) * s
//   s = max(alh[o], 1e-5); b = rint(clip(|bit[o]|,1,6)); qmax = max(2^(b-1)-1,1)
//
// R12: last unmeasured vertex of the constraint surface.
// 256-bit ld/st, batch 6 (192B/thr front-batched) at launch_bounds(256,4)
// = 64-reg budget -> 4 blocks/SM, theoretical 50% occ, 196KB outstanding/SM
// (R8: 128B/thr @ 62.5% = 160KB -> 6.22 TB/s; R9: 256B/thr @ 37.5% = 192KB
// -> 5.51 TB/s). Tests whether the occ slope has flattened by 50%.
// Reg audit vs the R10 serialization trap: 48 data + ~14 overhead = ~62 <= 64.
// Tiling: 5636096 vec8 = 3669*1536 + 512 -> 3670 blocks, per-item bounds
// predicate (only the last block diverges).

#define VEC8_PER_ROW 1376u
#define NTHR         256
#define BATCH        6
#define CHUNK        (NTHR * BATCH)          // 1536 vec8
#define NBLK         3670
#define TOTAL_VEC8   5636096u

struct f8 { float4 a, b; };

__device__ __forceinline__ f8 ldg256_cs(const float* p)
{
    f8 r;
    asm volatile("ld.global.cs.v8.f32 {%0,%1,%2,%3,%4,%5,%6,%7}, [%8];"
                 : "=f"(r.a.x), "=f"(r.a.y), "=f"(r.a.z), "=f"(r.a.w),
                   "=f"(r.b.x), "=f"(r.b.y), "=f"(r.b.z), "=f"(r.b.w)
                 : "l"(p));
    return r;
}

__device__ __forceinline__ void stg256_cs(float* p, f8 v)
{
    asm volatile("st.global.cs.v8.f32 [%0], {%1,%2,%3,%4,%5,%6,%7,%8};"
                 :: "l"(p),
                    "f"(v.a.x), "f"(v.a.y), "f"(v.a.z), "f"(v.a.w),
                    "f"(v.b.x), "f"(v.b.y), "f"(v.b.z), "f"(v.b.w)
                 : "memory");
}

__device__ __forceinline__ void row_params(unsigned idx8,
                                           const float* __restrict__ alh,
                                           const float* __restrict__ bit,
                                           float& s, float& qmax)
{
    const unsigned r = idx8 / VEC8_PER_ROW;   // warp-uniform; const-div
    s = fmaxf(alh[r], 1e-5f);
    const float b = rintf(fminf(fmaxf(fabsf(bit[r]), 1.0f), 6.0f));
    qmax = fmaxf(exp2f(b - 1.0f) - 1.0f, 1.0f);
}

__device__ __forceinline__ float qf(float x, float s, float qmin, float qmax)
{
    // True IEEE divide: rint decisions must match the reference exactly.
    return fminf(fmaxf(rintf(x / s), qmin), qmax) * s;
}

__device__ __forceinline__ f8 quant8(f8 v, float s, float qmax)
{
    const float qmin = -qmax;
    v.a.x = qf(v.a.x, s, qmin, qmax);  v.a.y = qf(v.a.y, s, qmin, qmax);
    v.a.z = qf(v.a.z, s, qmin, qmax);  v.a.w = qf(v.a.w, s, qmin, qmax);
    v.b.x = qf(v.b.x, s, qmin, qmax);  v.b.y = qf(v.b.y, s, qmin, qmax);
    v.b.z = qf(v.b.z, s, qmin, qmax);  v.b.w = qf(v.b.w, s, qmin, qmax);
    return v;
}

__global__ __launch_bounds__(NTHR, 4)
void fake_quant_kernel(const float* __restrict__ w,
                       const float* __restrict__ alh,
                       const float* __restrict__ bit,
                       float* __restrict__ out)
{
    const unsigned base = blockIdx.x * CHUNK + threadIdx.x;   // vec8 index

    // Front-batch all 6 256-bit loads (predicated; full in 3669/3670 blocks).
    f8 v[BATCH];
    #pragma unroll
    for (int i = 0; i < BATCH; i++) {
        const unsigned idx8 = base + i * NTHR;
        if (idx8 < TOTAL_VEC8)
            v[i] = ldg256_cs(w + (size_t)idx8 * 8u);
    }

    #pragma unroll
    for (int i = 0; i < BATCH; i++) {
        const unsigned idx8 = base + i * NTHR;
        if (idx8 < TOTAL_VEC8) {
            float s, qmax;
            row_params(idx8, alh, bit, s, qmax);
            stg256_cs(out + (size_t)idx8 * 8u, quant8(v[i], s, qmax));
        }
    }
}

extern "C" void kernel_launch(void* const* d_in, const int* in_sizes, int n_in,
                              void* d_out, int out_size)
{
    const float* w   = (const float*)d_in[0];  // weight [4096, 11008]
    const float* alh = (const float*)d_in[1];  // [4096, 1]
    const float* bit = (const float*)d_in[2];  // [4096, 1]
    float* out = (float*)d_out;

    fake_quant_kernel<<<NBLK, NTHR>>>(w, alh, bit, out);
}

// round 13
// speedup vs baseline: 1.0393x; 1.0393x over previous
#include <cuda_runtime.h>
#include <cuda_bf16.h>
#include <cstdint>

// u_quant_weight_linear: out[o,i] = clip(rint(w[o,i]/s), -qmax, qmax) * s
//   s = max(alh[o], 1e-5); b = rint(clip(|bit[o]|,1,6)); qmax = max(2^(b-1)-1,1)
//
// FINAL (= R8; measured optimum: 48.99us kernel / 6.22 TB/s / 78.5% DRAM,
// re-validated R11 at 49.70us / 6.14 TB/s — within run-to-run noise).
//
// Design: 256-bit global ld/st (Blackwell LDG.E.256/STG.E.256), batch 4
// front-batched per thread (128B genuinely in flight), 5504 blocks x 256 thr,
// zero tail (4096 rows * 1376 vec8 = 5504 * 1024 exactly).
// launch_bounds(256,5) -> 48 regs: holds the full load batch in registers
// (tighter caps make ptxas serialize the loads — R6/R10), 5 blocks/SM.
//
// Constraint surface mapped over 11 measured configs — every axis probed
// both directions bends back below R8:
//   deeper batch   (R9: 256B/thr @ 33% occ)   -> 5.51 TB/s (occupancy floor)
//   mid batch      (R12: 192B/thr @ 44% occ)  -> 5.76 TB/s (occ slope steep)
//   higher occ     (R10: 40-reg cap, 63% occ) -> 5.60 TB/s (load serialization)
//   128-bit twin   (R5: same shape)           -> 6.05 TB/s (2x LSU instr cost)
//   bulk-async     (R7: TMA 4-stage pipeline) -> 4.91 TB/s (epilogue-paced)
//
// Per-item row index via const-div (warp-uniform: 1376 % 32 == 0; alh/bit
// loads broadcast L1 hits). True IEEE divide in the quantizer so rint
// decisions match the reference bit-for-bit (rel_err 0.0 on every bench).

#define VEC8_PER_ROW 1376u
#define NTHR         256
#define BATCH        4
#define CHUNK        (NTHR * BATCH)          // 1024 vec8
#define NBLK         5504                     // 5504*1024 = 5636096 exactly

struct f8 { float4 a, b; };

__device__ __forceinline__ f8 ldg256_cs(const float* p)
{
    f8 r;
    asm volatile("ld.global.cs.v8.f32 {%0,%1,%2,%3,%4,%5,%6,%7}, [%8];"
                 : "=f"(r.a.x), "=f"(r.a.y), "=f"(r.a.z), "=f"(r.a.w),
                   "=f"(r.b.x), "=f"(r.b.y), "=f"(r.b.z), "=f"(r.b.w)
                 : "l"(p));
    return r;
}

__device__ __forceinline__ void stg256_cs(float* p, f8 v)
{
    asm volatile("st.global.cs.v8.f32 [%0], {%1,%2,%3,%4,%5,%6,%7,%8};"
                 :: "l"(p),
                    "f"(v.a.x), "f"(v.a.y), "f"(v.a.z), "f"(v.a.w),
                    "f"(v.b.x), "f"(v.b.y), "f"(v.b.z), "f"(v.b.w)
                 : "memory");
}

__device__ __forceinline__ void row_params(unsigned idx8,
                                           const float* __restrict__ alh,
                                           const float* __restrict__ bit,
                                           float& s, float& qmax)
{
    const unsigned r = idx8 / VEC8_PER_ROW;   // warp-uniform; const-div
    s = fmaxf(alh[r], 1e-5f);
    const float b = rintf(fminf(fmaxf(fabsf(bit[r]), 1.0f), 6.0f));
    qmax = fmaxf(exp2f(b - 1.0f) - 1.0f, 1.0f);
}

__device__ __forceinline__ float qf(float x, float s, float qmin, float qmax)
{
    // True IEEE divide: rint decisions must match the reference exactly.
    return fminf(fmaxf(rintf(x / s), qmin), qmax) * s;
}

__device__ __forceinline__ f8 quant8(f8 v, float s, float qmax)
{
    const float qmin = -qmax;
    v.a.x = qf(v.a.x, s, qmin, qmax);  v.a.y = qf(v.a.y, s, qmin, qmax);
    v.a.z = qf(v.a.z, s, qmin, qmax);  v.a.w = qf(v.a.w, s, qmin, qmax);
    v.b.x = qf(v.b.x, s, qmin, qmax);  v.b.y = qf(v.b.y, s, qmin, qmax);
    v.b.z = qf(v.b.z, s, qmin, qmax);  v.b.w = qf(v.b.w, s, qmin, qmax);
    return v;
}

__global__ __launch_bounds__(NTHR, 5)
void fake_quant_kernel(const float* __restrict__ w,
                       const float* __restrict__ alh,
                       const float* __restrict__ bit,
                       float* __restrict__ out)
{
    const unsigned base = blockIdx.x * CHUNK + threadIdx.x;   // vec8 index

    // Front-batch all 4 256-bit loads: 128B genuinely in flight per thread.
    f8 v[BATCH];
    #pragma unroll
    for (int i = 0; i < BATCH; i++)
        v[i] = ldg256_cs(w + (size_t)(base + i * NTHR) * 8u);

    #pragma unroll
    for (int i = 0; i < BATCH; i++) {
        const unsigned idx8 = base + i * NTHR;
        float s, qmax;
        row_params(idx8, alh, bit, s, qmax);
        stg256_cs(out + (size_t)idx8 * 8u, quant8(v[i], s, qmax));
    }
}

extern "C" void kernel_launch(void* const* d_in, const int* in_sizes, int n_in,
                              void* d_out, int out_size)
{
    const float* w   = (const float*)d_in[0];  // weight [4096, 11008]
    const float* alh = (const float*)d_in[1];  // [4096, 1]
    const float* bit = (const float*)d_in[2];  // [4096, 1]
    float* out = (float*)d_out;

    fake_quant_kernel<<<NBLK, NTHR>>>(w, alh, bit, out);
}